// round 11
// baseline (speedup 1.0000x reference)
#include <cuda_runtime.h>
#include <cstdint>

#define BB 16
#define TT 32
#define FF 8
#define SS 256
#define HH 512
#define K0 (FF + HH)   // 520

// ---------------- device scratch (static, no allocation) ----------------
__device__ float g_encW2[BB * SS * HH];   // 8 MB, enc @ W2^T (step-invariant)
__device__ float g_hW1[BB * HH];          // h_top @ W1^T + attn_b
__device__ float g_scores[BB * SS];
__device__ float g_weighted[BB * HH];
__device__ float g_xin[BB * FF];
__device__ float g_h0[2][BB * HH];        // ping-pong
__device__ float g_h1[2][BB * HH];

// ---------------- helpers ----------------
__device__ __forceinline__ float2 ffma2(float2 a, float2 b, float2 c) {
    unsigned long long A = *reinterpret_cast<unsigned long long*>(&a);
    unsigned long long Bv = *reinterpret_cast<unsigned long long*>(&b);
    unsigned long long C = *reinterpret_cast<unsigned long long*>(&c);
    unsigned long long D;
    asm("fma.rn.f32x2 %0, %1, %2, %3;" : "=l"(D) : "l"(A), "l"(Bv), "l"(C));
    return *reinterpret_cast<float2*>(&D);
}

__device__ __forceinline__ float fast_tanh(float x) {
    float e = __expf(2.0f * x);
    return 1.0f - __fdividef(2.0f, e + 1.0f);
}
__device__ __forceinline__ float fast_sig(float x) {
    return __fdividef(1.0f, 1.0f + __expf(-x));
}

// ---------------- init: copy initial state ----------------
__global__ void kInit(const float* __restrict__ target, const float* __restrict__ hidden0) {
    int idx = blockIdx.x * blockDim.x + threadIdx.x;
    if (idx < BB * HH) {
        g_h0[0][idx] = hidden0[idx];
        g_h1[0][idx] = hidden0[BB * HH + idx];
    }
    if (idx < BB * FF) {
        int b = idx >> 3, f = idx & 7;
        g_xin[idx] = target[b * TT * FF + f];
    }
}

// ---------------- encW2 = enc @ W2^T  (M=4096,N=512,K=512) ----------------
// 64x64 tile, K-tile 32, 256 threads, f32x2 packed FMA (2 FMA/inst).
__global__ void __launch_bounds__(256) kEncW2(const float* __restrict__ enc,
                                              const float* __restrict__ attnW) {
    __shared__ float As[32][68];  // [k][m]
    __shared__ float Bs[32][72];  // [k][j]
    int Mblk = blockIdx.y * 64;
    int Nblk = blockIdx.x * 64;
    int tid = threadIdx.x;
    int tx = tid & 15, ty = tid >> 4;

    float2 acc[4][2];
#pragma unroll
    for (int i = 0; i < 4; i++) { acc[i][0] = make_float2(0.f, 0.f); acc[i][1] = make_float2(0.f, 0.f); }

    const float* Ag = enc + (size_t)Mblk * 512;
    const float* Bg = attnW + (size_t)Nblk * 1024 + 512;  // W2 = attn_W[:, H:]

    for (int k0 = 0; k0 < 512; k0 += 32) {
#pragma unroll
        for (int r = 0; r < 2; r++) {
            int i = r * 256 + tid;
            int m = i >> 3, g = i & 7;
            float4 v = *reinterpret_cast<const float4*>(Ag + m * 512 + k0 + g * 4);
            As[g * 4 + 0][m] = v.x; As[g * 4 + 1][m] = v.y;
            As[g * 4 + 2][m] = v.z; As[g * 4 + 3][m] = v.w;
            float4 u = *reinterpret_cast<const float4*>(Bg + m * 1024 + k0 + g * 4);
            Bs[g * 4 + 0][m] = u.x; Bs[g * 4 + 1][m] = u.y;
            Bs[g * 4 + 2][m] = u.z; Bs[g * 4 + 3][m] = u.w;
        }
        __syncthreads();
#pragma unroll
        for (int kk = 0; kk < 32; kk++) {
            float4 a4 = *reinterpret_cast<const float4*>(&As[kk][ty * 4]);
            float2 b0 = *reinterpret_cast<const float2*>(&Bs[kk][tx * 4]);
            float2 b1 = *reinterpret_cast<const float2*>(&Bs[kk][tx * 4 + 2]);
            float2 aa;
            aa.x = aa.y = a4.x; acc[0][0] = ffma2(aa, b0, acc[0][0]); acc[0][1] = ffma2(aa, b1, acc[0][1]);
            aa.x = aa.y = a4.y; acc[1][0] = ffma2(aa, b0, acc[1][0]); acc[1][1] = ffma2(aa, b1, acc[1][1]);
            aa.x = aa.y = a4.z; acc[2][0] = ffma2(aa, b0, acc[2][0]); acc[2][1] = ffma2(aa, b1, acc[2][1]);
            aa.x = aa.y = a4.w; acc[3][0] = ffma2(aa, b0, acc[3][0]); acc[3][1] = ffma2(aa, b1, acc[3][1]);
        }
        __syncthreads();
    }
#pragma unroll
    for (int i = 0; i < 4; i++) {
        float* row = g_encW2 + (size_t)(Mblk + ty * 4 + i) * 512 + Nblk + tx * 4;
        *reinterpret_cast<float2*>(row) = acc[i][0];
        *reinterpret_cast<float2*>(row + 2) = acc[i][1];
    }
}

// ---------------- scores: warp per (b,s) ----------------
__global__ void __launch_bounds__(256) kScore(const float* __restrict__ v_w) {
    __shared__ float hs[HH];
    __shared__ float vs[HH];
    int b = blockIdx.y;
    int tid = threadIdx.x;
    for (int k = tid; k < HH; k += 256) { hs[k] = g_hW1[b * HH + k]; vs[k] = v_w[k]; }
    __syncthreads();
    int w = tid >> 5, l = tid & 31;
    int s = blockIdx.x * 8 + w;
    const float* e = g_encW2 + (size_t)(b * SS + s) * HH;
    float acc = 0.f;
#pragma unroll
    for (int i = 0; i < 16; i++) {
        int k = l + 32 * i;
        float t = fast_tanh(e[k] + hs[k]);
        acc += t * vs[k];
    }
#pragma unroll
    for (int off = 16; off > 0; off >>= 1) acc += __shfl_xor_sync(0xffffffffu, acc, off);
    if (l == 0) g_scores[b * SS + s] = acc;
}

// ---------------- softmax + weighted sum: block per (b, 128-h chunk) ----------------
__global__ void __launch_bounds__(256) kWeighted(const float* __restrict__ enc) {
    __shared__ float w_s[SS];
    __shared__ float red[256];
    int b = blockIdx.y;
    int hc = blockIdx.x;
    int tid = threadIdx.x;

    float sc = g_scores[b * SS + tid];
    red[tid] = sc; __syncthreads();
    for (int o = 128; o > 0; o >>= 1) { if (tid < o) red[tid] = fmaxf(red[tid], red[tid + o]); __syncthreads(); }
    float mx = red[0]; __syncthreads();
    float ex = __expf(sc - mx);
    red[tid] = ex; __syncthreads();
    for (int o = 128; o > 0; o >>= 1) { if (tid < o) red[tid] += red[tid + o]; __syncthreads(); }
    float inv = __fdividef(1.f, red[0]);
    __syncthreads();
    w_s[tid] = ex * inv;
    __syncthreads();

    int h = hc * 128 + (tid & 127);
    int half = tid >> 7;
    const float* ep = enc + (size_t)(b * SS + half * 128) * HH + h;
    float acc = 0.f;
#pragma unroll 4
    for (int s2 = 0; s2 < 128; s2++) acc += w_s[half * 128 + s2] * ep[(size_t)s2 * HH];
    red[tid] = acc; __syncthreads();
    if (half == 0) g_weighted[b * HH + h] = red[tid] + red[tid + 128];
}

// ---------------- GRU layer (generic): grid 128, 256 thr, dyn smem ----------------
// warp role: warps 0..3 -> gi for j0..j0+3 ; warps 4..7 -> gh for j0..j0+3
__global__ void __launch_bounds__(256) kGru(int layer, int p,
                                            const float* __restrict__ Wih,
                                            const float* __restrict__ Whh,
                                            const float* __restrict__ bih,
                                            const float* __restrict__ bhh) {
    extern __shared__ float sm[];
    const int K = (layer == 0) ? K0 : HH;
    float* xp = sm;                 // [8 bp][K] float2 (batch pairs)
    float* hp = sm + 16 * K;        // [8 bp][512] float2
    float* ex = hp + 16 * 512;      // [2 role][4 j][3 gate][16 b]

    const float* inA; int lenA; const float* inB;
    const float* hold; float* hnew;
    if (layer == 0) { inA = g_xin; lenA = FF; inB = g_weighted; hold = g_h0[p]; hnew = g_h0[1 - p]; }
    else            { inA = g_h0[1 - p]; lenA = HH; inB = nullptr; hold = g_h1[p]; hnew = g_h1[1 - p]; }

    int tid = threadIdx.x;
    for (int i = tid; i < 16 * K; i += 256) {
        int b = i / K; int k = i - b * K;
        float v = (k < lenA) ? inA[b * lenA + k] : inB[b * HH + (k - lenA)];
        xp[(b >> 1) * (2 * K) + 2 * k + (b & 1)] = v;
    }
    for (int i = tid; i < 16 * 512; i += 256) {
        int b = i >> 9; int k = i & 511;
        hp[(b >> 1) * 1024 + 2 * k + (b & 1)] = hold[b * HH + k];
    }
    __syncthreads();

    int w = tid >> 5, l = tid & 31;
    int jrel = w & 3;
    int role = w >> 2;             // 0 = gi (input), 1 = gh (hidden)
    int j = blockIdx.x * 4 + jrel;

    const float* Wm = role ? Whh : Wih;
    int Kr = role ? HH : K;
    const float2* src = reinterpret_cast<const float2*>(role ? hp : xp);
    int rowlen = role ? 512 : K;

    float2 a0[8], a1[8], a2[8];
#pragma unroll
    for (int bp = 0; bp < 8; bp++) { a0[bp] = make_float2(0.f, 0.f); a1[bp] = a0[bp]; a2[bp] = a0[bp]; }

    const float* wr = Wm + (size_t)j * Kr;
    const float* wz = Wm + (size_t)(j + 512) * Kr;
    const float* wn = Wm + (size_t)(j + 1024) * Kr;

    for (int k = l; k < Kr; k += 32) {
        float r_ = wr[k], z_ = wz[k], n_ = wn[k];
        float2 rr = make_float2(r_, r_), zz = make_float2(z_, z_), nn = make_float2(n_, n_);
#pragma unroll
        for (int bp = 0; bp < 8; bp++) {
            float2 x2 = src[bp * rowlen + k];
            a0[bp] = ffma2(x2, rr, a0[bp]);
            a1[bp] = ffma2(x2, zz, a1[bp]);
            a2[bp] = ffma2(x2, nn, a2[bp]);
        }
    }
#pragma unroll
    for (int off = 16; off > 0; off >>= 1) {
#pragma unroll
        for (int bp = 0; bp < 8; bp++) {
            a0[bp].x += __shfl_xor_sync(0xffffffffu, a0[bp].x, off);
            a0[bp].y += __shfl_xor_sync(0xffffffffu, a0[bp].y, off);
            a1[bp].x += __shfl_xor_sync(0xffffffffu, a1[bp].x, off);
            a1[bp].y += __shfl_xor_sync(0xffffffffu, a1[bp].y, off);
            a2[bp].x += __shfl_xor_sync(0xffffffffu, a2[bp].x, off);
            a2[bp].y += __shfl_xor_sync(0xffffffffu, a2[bp].y, off);
        }
    }
    if (l == 0) {
        float* dst = ex + (role * 4 + jrel) * 48;
#pragma unroll
        for (int bp = 0; bp < 8; bp++) {
            dst[2 * bp] = a0[bp].x;      dst[2 * bp + 1] = a0[bp].y;
            dst[16 + 2 * bp] = a1[bp].x; dst[16 + 2 * bp + 1] = a1[bp].y;
            dst[32 + 2 * bp] = a2[bp].x; dst[32 + 2 * bp + 1] = a2[bp].y;
        }
    }
    __syncthreads();
    if (tid < 64) {
        int b = tid & 15, jr = tid >> 4;
        int jj = blockIdx.x * 4 + jr;
        const float* gi = ex + jr * 48;
        const float* gh = ex + (4 + jr) * 48;
        float gir = gi[b], giz = gi[16 + b], gin = gi[32 + b];
        float ghr = gh[b], ghz = gh[16 + b], ghn = gh[32 + b];
        float r = fast_sig(gir + bih[jj] + ghr + bhh[jj]);
        float z = fast_sig(giz + bih[jj + 512] + ghz + bhh[jj + 512]);
        float n = fast_tanh(gin + bih[jj + 1024] + r * (ghn + bhh[jj + 1024]));
        float hprev = hp[(b >> 1) * 1024 + 2 * jj + (b & 1)];
        hnew[b * HH + jj] = (1.f - z) * n + z * hprev;
    }
}

// ---------------- tail: next-step hW1 (blocks 0..63) + output proj (block 64) ----------------
__global__ void __launch_bounds__(256) kTail(int pn, int t,
                                             const float* __restrict__ attnW,
                                             const float* __restrict__ attnb,
                                             const float* __restrict__ outW,
                                             const float* __restrict__ outb,
                                             float* __restrict__ dout) {
    __shared__ float hp[16 * HH];
    const float* h1 = g_h1[pn];
    int tid = threadIdx.x;

    if (blockIdx.x < 64) {
        for (int i = tid; i < 16 * 512; i += 256) {
            int b = i >> 9, k = i & 511;
            hp[(b >> 1) * 1024 + 2 * k + (b & 1)] = h1[b * HH + k];
        }
        __syncthreads();
        int w = tid >> 5, l = tid & 31;
        int j = blockIdx.x * 8 + w;
        const float2* hp2 = reinterpret_cast<const float2*>(hp);
        const float* wcol = attnW + (size_t)j * (2 * HH);  // W1[j][:]
        float2 acc[8];
#pragma unroll
        for (int bp = 0; bp < 8; bp++) acc[bp] = make_float2(0.f, 0.f);
        for (int k = l; k < HH; k += 32) {
            float wv = wcol[k];
            float2 ww = make_float2(wv, wv);
#pragma unroll
            for (int bp = 0; bp < 8; bp++) acc[bp] = ffma2(hp2[bp * 512 + k], ww, acc[bp]);
        }
#pragma unroll
        for (int off = 16; off > 0; off >>= 1) {
#pragma unroll
            for (int bp = 0; bp < 8; bp++) {
                acc[bp].x += __shfl_xor_sync(0xffffffffu, acc[bp].x, off);
                acc[bp].y += __shfl_xor_sync(0xffffffffu, acc[bp].y, off);
            }
        }
        if (l == 0) {
            float bb = attnb[j];
#pragma unroll
            for (int bp = 0; bp < 8; bp++) {
                g_hW1[(2 * bp) * HH + j] = acc[bp].x + bb;
                g_hW1[(2 * bp + 1) * HH + j] = acc[bp].y + bb;
            }
        }
    } else if (t >= 0) {
        int b = tid >> 3, f = tid & 7;
        bool act = (tid < 128);
        float acc = 0.f;
        if (act) {
            const float* wrow = outW + f * (2 * HH + FF);
            acc = outb[f];
            const float2* w2 = reinterpret_cast<const float2*>(wrow);
            const float2* h2 = reinterpret_cast<const float2*>(h1 + b * HH);
            const float2* g2 = reinterpret_cast<const float2*>(g_weighted + b * HH);
#pragma unroll 4
            for (int c = 0; c < HH / 2; c++) { float2 wv = w2[c]; float2 hv = h2[c]; acc += wv.x * hv.x + wv.y * hv.y; }
#pragma unroll 4
            for (int c = 0; c < HH / 2; c++) { float2 wv = w2[HH / 2 + c]; float2 gv = g2[c]; acc += wv.x * gv.x + wv.y * gv.y; }
#pragma unroll
            for (int c = 0; c < FF; c++) acc += wrow[2 * HH + c] * g_xin[b * FF + c];
            acc = fmaxf(acc, 0.f);
            dout[(b * TT + t) * FF + f] = acc;
        }
        __syncthreads();           // all reads of g_xin done before overwrite
        if (act) g_xin[b * FF + f] = acc;   // next_in = out (TGT_IDX covers all F)
    }
}

// ---------------- launch ----------------
extern "C" void kernel_launch(void* const* d_in, const int* in_sizes, int n_in,
                              void* d_out, int out_size) {
    (void)in_sizes; (void)n_in; (void)out_size;
    const float* target  = (const float*)d_in[0];
    const float* hidden0 = (const float*)d_in[1];
    const float* enc     = (const float*)d_in[2];
    const float* attnW   = (const float*)d_in[3];
    const float* attnb   = (const float*)d_in[4];
    const float* v_w     = (const float*)d_in[5];
    const float* Wih0    = (const float*)d_in[6];
    const float* Whh0    = (const float*)d_in[7];
    const float* bih0    = (const float*)d_in[8];
    const float* bhh0    = (const float*)d_in[9];
    const float* Wih1    = (const float*)d_in[10];
    const float* Whh1    = (const float*)d_in[11];
    const float* bih1    = (const float*)d_in[12];
    const float* bhh1    = (const float*)d_in[13];
    const float* outW    = (const float*)d_in[14];
    const float* outb    = (const float*)d_in[15];
    float* dout = (float*)d_out;

    const int smem0 = (16 * K0 + 16 * 512 + 2 * 4 * 3 * 16) * 4;  // 67584 B
    const int smem1 = (16 * HH + 16 * 512 + 2 * 4 * 3 * 16) * 4;  // 66560 B
    cudaFuncSetAttribute(kGru, cudaFuncAttributeMaxDynamicSharedMemorySize, smem0);

    kInit<<<32, 256>>>(target, hidden0);
    kEncW2<<<dim3(8, 64), 256>>>(enc, attnW);
    kTail<<<65, 256>>>(0, -1, attnW, attnb, outW, outb, dout);  // initial hW1 from hidden0[1]

    for (int t = 0; t < TT; t++) {
        int p = t & 1;
        int pn = 1 - p;
        kScore<<<dim3(32, 16), 256>>>(v_w);
        kWeighted<<<dim3(4, 16), 256>>>(enc);
        kGru<<<128, 256, smem0>>>(0, p, Wih0, Whh0, bih0, bhh0);
        kGru<<<128, 256, smem1>>>(1, p, Wih1, Whh1, bih1, bhh1);
        kTail<<<65, 256>>>(pn, t, attnW, attnb, outW, outb, dout);
    }
}

// round 12
// speedup vs baseline: 1.5258x; 1.5258x over previous
#include <cuda_runtime.h>
#include <cstdint>

#define BB 16
#define TT 32
#define FF 8
#define SS 256
#define HH 512
#define K0 (FF + HH)   // 520
#define GRID 148
#define NTH 512

// ---------------- device scratch (static, no allocation) ----------------
__device__ float g_encW2[BB * SS * HH];   // 8 MB, enc @ W2^T (step-invariant)
__device__ float g_hW1[BB * HH];
__device__ float g_scores[BB * SS];
__device__ float g_weighted[BB * HH];
__device__ float g_xin[BB * FF];
__device__ float g_h0[2][BB * HH];
__device__ float g_h1[2][BB * HH];
__device__ int   g_bar_count;  // self-resetting
__device__ int   g_bar_gen;    // monotonically increasing across replays

// ---------------- helpers ----------------
__device__ __forceinline__ float2 ffma2(float2 a, float2 b, float2 c) {
    unsigned long long A = *reinterpret_cast<unsigned long long*>(&a);
    unsigned long long Bv = *reinterpret_cast<unsigned long long*>(&b);
    unsigned long long C = *reinterpret_cast<unsigned long long*>(&c);
    unsigned long long D;
    asm("fma.rn.f32x2 %0, %1, %2, %3;" : "=l"(D) : "l"(A), "l"(Bv), "l"(C));
    return *reinterpret_cast<float2*>(&D);
}
__device__ __forceinline__ float fast_tanh(float x) {
    float e = __expf(2.0f * x);
    return 1.0f - __fdividef(2.0f, e + 1.0f);
}
__device__ __forceinline__ float fast_sig(float x) {
    return __fdividef(1.0f, 1.0f + __expf(-x));
}

// grid barrier: release on arrive, acquire on observe. NO __threadfence
// (gpu-scope fence emits CCTL.IVALL and would flush L1D, killing the
// L1-residency of weights/enc/encW2 across steps).
__device__ __forceinline__ void gridbar() {
    __syncthreads();
    if (threadIdx.x == 0) {
        int gen;
        asm volatile("ld.relaxed.gpu.s32 %0, [%1];" : "=r"(gen) : "l"(&g_bar_gen) : "memory");
        int prev;
        asm volatile("atom.release.gpu.add.s32 %0, [%1], %2;"
                     : "=r"(prev) : "l"(&g_bar_count), "r"(1) : "memory");
        if (prev == GRID - 1) {
            asm volatile("st.relaxed.gpu.s32 [%0], %1;" :: "l"(&g_bar_count), "r"(0) : "memory");
            asm volatile("st.release.gpu.s32 [%0], %1;" :: "l"(&g_bar_gen), "r"(gen + 1) : "memory");
        } else {
            int cur;
            do {
                asm volatile("ld.acquire.gpu.s32 %0, [%1];" : "=r"(cur) : "l"(&g_bar_gen) : "memory");
            } while (cur == gen);
        }
    }
    __syncthreads();
}

__device__ __forceinline__ float  lcg(const float* p)  { return __ldcg(p); }
__device__ __forceinline__ float2 lcg2(const float* p) { return __ldcg(reinterpret_cast<const float2*>(p)); }

// ---------------- encW2 = enc @ W2^T  (prologue GEMM, unchanged) ----------------
__global__ void __launch_bounds__(256) kEncW2(const float* __restrict__ enc,
                                              const float* __restrict__ attnW) {
    __shared__ float As[32][68];
    __shared__ float Bs[32][72];
    int Mblk = blockIdx.y * 64;
    int Nblk = blockIdx.x * 64;
    int tid = threadIdx.x;
    int tx = tid & 15, ty = tid >> 4;

    float2 acc[4][2];
#pragma unroll
    for (int i = 0; i < 4; i++) { acc[i][0] = make_float2(0.f, 0.f); acc[i][1] = make_float2(0.f, 0.f); }

    const float* Ag = enc + (size_t)Mblk * 512;
    const float* Bg = attnW + (size_t)Nblk * 1024 + 512;

    for (int k0 = 0; k0 < 512; k0 += 32) {
#pragma unroll
        for (int r = 0; r < 2; r++) {
            int i = r * 256 + tid;
            int m = i >> 3, g = i & 7;
            float4 v = *reinterpret_cast<const float4*>(Ag + m * 512 + k0 + g * 4);
            As[g * 4 + 0][m] = v.x; As[g * 4 + 1][m] = v.y;
            As[g * 4 + 2][m] = v.z; As[g * 4 + 3][m] = v.w;
            float4 u = *reinterpret_cast<const float4*>(Bg + m * 1024 + k0 + g * 4);
            Bs[g * 4 + 0][m] = u.x; Bs[g * 4 + 1][m] = u.y;
            Bs[g * 4 + 2][m] = u.z; Bs[g * 4 + 3][m] = u.w;
        }
        __syncthreads();
#pragma unroll
        for (int kk = 0; kk < 32; kk++) {
            float4 a4 = *reinterpret_cast<const float4*>(&As[kk][ty * 4]);
            float2 b0 = *reinterpret_cast<const float2*>(&Bs[kk][tx * 4]);
            float2 b1 = *reinterpret_cast<const float2*>(&Bs[kk][tx * 4 + 2]);
            float2 aa;
            aa.x = aa.y = a4.x; acc[0][0] = ffma2(aa, b0, acc[0][0]); acc[0][1] = ffma2(aa, b1, acc[0][1]);
            aa.x = aa.y = a4.y; acc[1][0] = ffma2(aa, b0, acc[1][0]); acc[1][1] = ffma2(aa, b1, acc[1][1]);
            aa.x = aa.y = a4.z; acc[2][0] = ffma2(aa, b0, acc[2][0]); acc[2][1] = ffma2(aa, b1, acc[2][1]);
            aa.x = aa.y = a4.w; acc[3][0] = ffma2(aa, b0, acc[3][0]); acc[3][1] = ffma2(aa, b1, acc[3][1]);
        }
        __syncthreads();
    }
#pragma unroll
    for (int i = 0; i < 4; i++) {
        float* row = g_encW2 + (size_t)(Mblk + ty * 4 + i) * 512 + Nblk + tx * 4;
        *reinterpret_cast<float2*>(row) = acc[i][0];
        *reinterpret_cast<float2*>(row + 2) = acc[i][1];
    }
}

// ================== persistent-kernel phases ==================

// scores: warp per (b,s) pair, static partition -> encW2 slice L1-resident
__device__ __forceinline__ void scores_phase(const float* __restrict__ v_w) {
    int tid = threadIdx.x, w = tid >> 5, l = tid & 31;
    for (int pr = blockIdx.x * 16 + w; pr < BB * SS; pr += GRID * 16) {
        int b = pr >> 8;
        const float* e = g_encW2 + (size_t)pr * HH;
        const float* hr = g_hW1 + b * HH;
        float acc = 0.f;
#pragma unroll
        for (int i = 0; i < 16; i++) {
            int k = l + 32 * i;
            float x = e[k] + lcg(hr + k);
            acc += fast_tanh(x) * v_w[k];
        }
#pragma unroll
        for (int off = 16; off > 0; off >>= 1) acc += __shfl_xor_sync(0xffffffffu, acc, off);
        if (l == 0) g_scores[pr] = acc;
    }
}

// softmax (redundant per block) + weighted sum; block = (b, 64-h chunk)
__device__ __forceinline__ void weighted_phase(float* sm, const float* __restrict__ enc) {
    int bi = blockIdx.x;
    if (bi >= 128) return;
    int tid = threadIdx.x;
    int b = bi >> 3, hc = bi & 7;
    float* wsm = sm;         // 256
    float* red = sm + 256;   // 512

    float sc = (tid < 256) ? lcg(&g_scores[b * SS + tid]) : -3.4e38f;
    red[tid] = sc; __syncthreads();
    for (int o = 256; o > 0; o >>= 1) { if (tid < o) red[tid] = fmaxf(red[tid], red[tid + o]); __syncthreads(); }
    float mx = red[0]; __syncthreads();
    float e = (tid < 256) ? __expf(sc - mx) : 0.f;
    red[tid] = e; __syncthreads();
    for (int o = 256; o > 0; o >>= 1) { if (tid < o) red[tid] += red[tid + o]; __syncthreads(); }
    float inv = __fdividef(1.f, red[0]);
    __syncthreads();
    if (tid < 256) wsm[tid] = e * inv;
    __syncthreads();

    int h = hc * 64 + (tid & 63), sg = tid >> 6;
    const float* ep = enc + (size_t)b * SS * HH + h;
    float acc = 0.f;
#pragma unroll 4
    for (int s = sg; s < SS; s += 8) acc += wsm[s] * ep[(size_t)s * HH];
    red[tid] = acc; __syncthreads();
    if (sg < 4) red[tid] += red[tid + 256];
    __syncthreads();
    if (sg < 2) red[tid] += red[tid + 128];
    __syncthreads();
    if (sg == 0) g_weighted[b * HH + h] = red[tid] + red[tid + 64];
}

// GRU layer: 128 blocks x 4 j; 16 warps = {gi,gh} x {4 j} x {2 K-halves}
__device__ __forceinline__ void gru_phase(float* sm, int layer, int p,
                                          const float* __restrict__ Wih,
                                          const float* __restrict__ Whh,
                                          const float* __restrict__ bih,
                                          const float* __restrict__ bhh) {
    int bi = blockIdx.x;
    if (bi >= 128) return;
    int tid = threadIdx.x;
    const int K = (layer == 0) ? K0 : HH;
    float* xp = sm;                 // 16 x K (batch-pair packed)
    float* hp = sm + 16 * K;        // 16 x 512
    float* ex = hp + 16 * 512;      // [role2][kh2][j4][gate3][b16]

    const float* inA; int lenA; const float* inB;
    const float* hold; float* hnew;
    if (layer == 0) { inA = g_xin; lenA = FF; inB = g_weighted; hold = g_h0[p]; hnew = g_h0[1 - p]; }
    else            { inA = g_h0[1 - p]; lenA = HH; inB = nullptr; hold = g_h1[p]; hnew = g_h1[1 - p]; }

    for (int i = tid; i < 16 * K; i += NTH) {
        int b = i / K; int k = i - b * K;
        float v = (k < lenA) ? lcg(inA + b * lenA + k) : lcg(inB + b * HH + (k - lenA));
        xp[(b >> 1) * (2 * K) + 2 * k + (b & 1)] = v;
    }
    for (int i = tid; i < 16 * 512; i += NTH) {
        int b = i >> 9; int k = i & 511;
        hp[(b >> 1) * 1024 + 2 * k + (b & 1)] = lcg(hold + b * HH + k);
    }
    __syncthreads();

    int w = tid >> 5, l = tid & 31;
    int jrel = w & 3;
    int role = (w >> 2) & 1;       // 0 = gi (input mat), 1 = gh (hidden mat)
    int kh = w >> 3;               // K-half
    int j = bi * 4 + jrel;

    const float* Wm = role ? Whh : Wih;
    int Kr = role ? HH : K;
    const float2* src = reinterpret_cast<const float2*>(role ? hp : xp);
    int rowlen = role ? 512 : K;

    float2 a0[8], a1[8], a2[8];
#pragma unroll
    for (int bp = 0; bp < 8; bp++) { a0[bp] = make_float2(0.f, 0.f); a1[bp] = a0[bp]; a2[bp] = a0[bp]; }

    const float* wr = Wm + (size_t)j * Kr;
    const float* wz = wr + (size_t)512 * Kr;
    const float* wn = wz + (size_t)512 * Kr;

    for (int k = l + kh * 32; k < Kr; k += 64) {
        float r_ = wr[k], z_ = wz[k], n_ = wn[k];
        float2 rr = make_float2(r_, r_), zz = make_float2(z_, z_), nn = make_float2(n_, n_);
#pragma unroll
        for (int bp = 0; bp < 8; bp++) {
            float2 x2 = src[bp * rowlen + k];
            a0[bp] = ffma2(x2, rr, a0[bp]);
            a1[bp] = ffma2(x2, zz, a1[bp]);
            a2[bp] = ffma2(x2, nn, a2[bp]);
        }
    }
#pragma unroll
    for (int off = 16; off > 0; off >>= 1) {
#pragma unroll
        for (int bp = 0; bp < 8; bp++) {
            a0[bp].x += __shfl_xor_sync(0xffffffffu, a0[bp].x, off);
            a0[bp].y += __shfl_xor_sync(0xffffffffu, a0[bp].y, off);
            a1[bp].x += __shfl_xor_sync(0xffffffffu, a1[bp].x, off);
            a1[bp].y += __shfl_xor_sync(0xffffffffu, a1[bp].y, off);
            a2[bp].x += __shfl_xor_sync(0xffffffffu, a2[bp].x, off);
            a2[bp].y += __shfl_xor_sync(0xffffffffu, a2[bp].y, off);
        }
    }
    if (l == 0) {
        float* dst = ex + ((role * 2 + kh) * 4 + jrel) * 48;
#pragma unroll
        for (int bp = 0; bp < 8; bp++) {
            dst[2 * bp] = a0[bp].x;      dst[2 * bp + 1] = a0[bp].y;
            dst[16 + 2 * bp] = a1[bp].x; dst[16 + 2 * bp + 1] = a1[bp].y;
            dst[32 + 2 * bp] = a2[bp].x; dst[32 + 2 * bp + 1] = a2[bp].y;
        }
    }
    __syncthreads();
    if (tid < 64) {
        int b = tid & 15, jr = tid >> 4;
        int jj = bi * 4 + jr;
        const float* gi0 = ex + ((0 * 2 + 0) * 4 + jr) * 48;
        const float* gi1 = ex + ((0 * 2 + 1) * 4 + jr) * 48;
        const float* gh0 = ex + ((1 * 2 + 0) * 4 + jr) * 48;
        const float* gh1 = ex + ((1 * 2 + 1) * 4 + jr) * 48;
        float gir = gi0[b] + gi1[b], giz = gi0[16 + b] + gi1[16 + b], gin = gi0[32 + b] + gi1[32 + b];
        float ghr = gh0[b] + gh1[b], ghz = gh0[16 + b] + gh1[16 + b], ghn = gh0[32 + b] + gh1[32 + b];
        float r = fast_sig(gir + bih[jj] + ghr + bhh[jj]);
        float z = fast_sig(giz + bih[jj + 512] + ghz + bhh[jj + 512]);
        float n = fast_tanh(gin + bih[jj + 1024] + r * (ghn + bhh[jj + 1024]));
        float hprev = hp[(b >> 1) * 1024 + 2 * jj + (b & 1)];
        hnew[b * HH + jj] = (1.f - z) * n + z * hprev;
    }
}

// tail: blocks 0..63 compute next-step hW1 (8 j each, K split across warp pairs);
// block 64 does out-proj + xin update (K split 4-ways across thread groups).
__device__ __forceinline__ void tail_phase(float* sm, int pn, int t,
                                           const float* __restrict__ attnW,
                                           const float* __restrict__ attnb,
                                           const float* __restrict__ outW,
                                           const float* __restrict__ outb,
                                           float* __restrict__ dout) {
    int bi = blockIdx.x;
    int tid = threadIdx.x;
    const float* h1 = g_h1[pn];

    if (bi < 64) {
        float* hp = sm;             // 16 x 512 packed pairs
        float* ex = sm + 16 * 512;  // [kh2][j8][b16]
        for (int i = tid; i < 16 * 512; i += NTH) {
            int b = i >> 9, k = i & 511;
            hp[(b >> 1) * 1024 + 2 * k + (b & 1)] = lcg(h1 + b * HH + k);
        }
        __syncthreads();
        int w = tid >> 5, l = tid & 31;
        int jrel = w & 7, kh = w >> 3;
        int j = bi * 8 + jrel;
        const float2* hp2 = reinterpret_cast<const float2*>(hp);
        const float* wcol = attnW + (size_t)j * (2 * HH);
        float2 acc[8];
#pragma unroll
        for (int bp = 0; bp < 8; bp++) acc[bp] = make_float2(0.f, 0.f);
        for (int k = l + kh * 32; k < HH; k += 64) {
            float wv = wcol[k];
            float2 ww = make_float2(wv, wv);
#pragma unroll
            for (int bp = 0; bp < 8; bp++) acc[bp] = ffma2(hp2[bp * 512 + k], ww, acc[bp]);
        }
#pragma unroll
        for (int off = 16; off > 0; off >>= 1) {
#pragma unroll
            for (int bp = 0; bp < 8; bp++) {
                acc[bp].x += __shfl_xor_sync(0xffffffffu, acc[bp].x, off);
                acc[bp].y += __shfl_xor_sync(0xffffffffu, acc[bp].y, off);
            }
        }
        if (l == 0) {
            float* dst = ex + (kh * 8 + jrel) * 16;
#pragma unroll
            for (int bp = 0; bp < 8; bp++) { dst[2 * bp] = acc[bp].x; dst[2 * bp + 1] = acc[bp].y; }
        }
        __syncthreads();
        if (tid < 128) {
            int b = tid & 15, jr = tid >> 4;
            int jj = bi * 8 + jr;
            g_hW1[b * HH + jj] = ex[jr * 16 + b] + ex[(8 + jr) * 16 + b] + attnb[jj];
        }
    } else if (bi == 64 && t >= 0) {
        float* red = sm;  // 512
        int out = tid & 127, kc = tid >> 7;
        int b = out >> 3, f = out & 7;
        const float* wrow = outW + f * (2 * HH + FF);
        float acc = 0.f;
        if (kc < 2) {
            const float2* w2 = reinterpret_cast<const float2*>(wrow + kc * 256);
            const float* h2 = h1 + b * HH + kc * 256;
#pragma unroll 8
            for (int c = 0; c < 128; c++) {
                float2 wv = w2[c]; float2 hv = lcg2(h2 + 2 * c);
                acc += wv.x * hv.x + wv.y * hv.y;
            }
        } else {
            const float2* w2 = reinterpret_cast<const float2*>(wrow + 512 + (kc - 2) * 256);
            const float* g2 = g_weighted + b * HH + (kc - 2) * 256;
#pragma unroll 8
            for (int c = 0; c < 128; c++) {
                float2 wv = w2[c]; float2 gv = lcg2(g2 + 2 * c);
                acc += wv.x * gv.x + wv.y * gv.y;
            }
            if (kc == 3) {
#pragma unroll
                for (int c = 0; c < FF; c++) acc += wrow[2 * HH + c] * lcg(&g_xin[b * FF + c]);
                acc += outb[f];
            }
        }
        red[tid] = acc;
        __syncthreads();   // all g_xin reads done
        if (kc == 0) {
            float v = red[out] + red[out + 128] + red[out + 256] + red[out + 384];
            v = fmaxf(v, 0.f);
            dout[(b * TT + t) * FF + f] = v;
            g_xin[out] = v;   // next_in = out (TGT_IDX covers all F)
        }
    }
}

// ================== persistent kernel ==================
__global__ void __launch_bounds__(NTH, 1)
kPersist(const float* __restrict__ target, const float* __restrict__ hidden0,
         const float* __restrict__ enc, const float* __restrict__ attnW,
         const float* __restrict__ attnb, const float* __restrict__ v_w,
         const float* __restrict__ Wih0, const float* __restrict__ Whh0,
         const float* __restrict__ bih0, const float* __restrict__ bhh0,
         const float* __restrict__ Wih1, const float* __restrict__ Whh1,
         const float* __restrict__ bih1, const float* __restrict__ bhh1,
         const float* __restrict__ outW, const float* __restrict__ outb,
         float* __restrict__ dout)
{
    extern __shared__ float sm[];
    int tid = threadIdx.x, bi = blockIdx.x;

    // init state
    for (int i = bi * NTH + tid; i < BB * HH; i += GRID * NTH) {
        g_h0[0][i] = hidden0[i];
        g_h1[0][i] = hidden0[BB * HH + i];
    }
    if (bi == 0 && tid < BB * FF) {
        int b = tid >> 3, f = tid & 7;
        g_xin[tid] = target[b * TT * FF + f];
    }
    gridbar();

    // initial hW1 from h1 parity 0
    tail_phase(sm, 0, -1, attnW, attnb, outW, outb, dout);
    gridbar();

    for (int t = 0; t < TT; t++) {
        int p = t & 1, pn = 1 - p;
        scores_phase(v_w);
        gridbar();
        weighted_phase(sm, enc);
        gridbar();
        gru_phase(sm, 0, p, Wih0, Whh0, bih0, bhh0);
        gridbar();
        gru_phase(sm, 1, p, Wih1, Whh1, bih1, bhh1);
        gridbar();
        tail_phase(sm, pn, t, attnW, attnb, outW, outb, dout);
        gridbar();
    }
}

// ---------------- launch ----------------
extern "C" void kernel_launch(void* const* d_in, const int* in_sizes, int n_in,
                              void* d_out, int out_size) {
    (void)in_sizes; (void)n_in; (void)out_size;
    const float* target  = (const float*)d_in[0];
    const float* hidden0 = (const float*)d_in[1];
    const float* enc     = (const float*)d_in[2];
    const float* attnW   = (const float*)d_in[3];
    const float* attnb   = (const float*)d_in[4];
    const float* v_w     = (const float*)d_in[5];
    const float* Wih0    = (const float*)d_in[6];
    const float* Whh0    = (const float*)d_in[7];
    const float* bih0    = (const float*)d_in[8];
    const float* bhh0    = (const float*)d_in[9];
    const float* Wih1    = (const float*)d_in[10];
    const float* Whh1    = (const float*)d_in[11];
    const float* bih1    = (const float*)d_in[12];
    const float* bhh1    = (const float*)d_in[13];
    const float* outW    = (const float*)d_in[14];
    const float* outb    = (const float*)d_in[15];
    float* dout = (float*)d_out;

    const int smem = (16 * K0 + 16 * 512 + 768) * 4;  // 69120 B
    static int cfg_done = 0;
    if (!cfg_done) {
        cudaFuncSetAttribute(kPersist, cudaFuncAttributeMaxDynamicSharedMemorySize, smem);
        cfg_done = 1;
    }

    kEncW2<<<dim3(8, 64), 256>>>(enc, attnW);
    kPersist<<<GRID, NTH, smem>>>(target, hidden0, enc, attnW, attnb, v_w,
                                  Wih0, Whh0, bih0, bhh0,
                                  Wih1, Whh1, bih1, bhh1,
                                  outW, outb, dout);
}